// round 13
// baseline (speedup 1.0000x reference)
#include <cuda_runtime.h>
#include <cuda_fp16.h>
#include <cstdint>

#define DIM 256
#define HEADS 8
#define HD 32
#define N_TOK 64
#define IMG 256
#define BATCH 4
#define NWIN 1024
#define NPIX 262144
#define SCALE 0.17677669529663687f

// scratch (static device globals: allocation-free per harness rules)
__device__ __align__(256) __half g_qkv[201326592];  // [4096 win][3][64 tok][256 ch]
__device__ __align__(256) __half g_o[67108864];     // attn output (fp16, pre-rounded)
__device__ __align__(256) __half g_wq[196608];      // fp16 qkv_w
__device__ __align__(256) __half g_wp[65536];       // fp16 proj_w

extern __shared__ float dynsmem[];

__device__ __forceinline__ uint32_t pack_h2(float a, float b) {
    __half2 h = __floats2half2_rn(a, b);
    uint32_t r;
    memcpy(&r, &h, 4);
    return r;
}

__device__ __forceinline__ void mma_f16(float c[4], const uint32_t a[4],
                                        uint32_t b0, uint32_t b1) {
    asm volatile(
        "mma.sync.aligned.m16n8k16.row.col.f32.f16.f16.f32 "
        "{%0,%1,%2,%3}, {%4,%5,%6,%7}, {%8,%9}, {%0,%1,%2,%3};"
        : "+f"(c[0]), "+f"(c[1]), "+f"(c[2]), "+f"(c[3])
        : "r"(a[0]), "r"(a[1]), "r"(a[2]), "r"(a[3]), "r"(b0), "r"(b1));
}

__device__ __forceinline__ uint32_t smem_u32(const void* p) {
    uint32_t a;
    asm("{ .reg .u64 t; cvta.to.shared.u64 t, %1; cvt.u32.u64 %0, t; }"
        : "=r"(a) : "l"(p));
    return a;
}

#define LDSM_X4(R0, R1, R2, R3, ADDR) \
    asm volatile("ldmatrix.sync.aligned.m8n8.x4.shared.b16 {%0,%1,%2,%3}, [%4];" \
                 : "=r"(R0), "=r"(R1), "=r"(R2), "=r"(R3) : "r"(ADDR))

#define LDSM_X4_TRANS(R0, R1, R2, R3, ADDR) \
    asm volatile("ldmatrix.sync.aligned.m8n8.x4.trans.shared.b16 {%0,%1,%2,%3}, [%4];" \
                 : "=r"(R0), "=r"(R1), "=r"(R2), "=r"(R3) : "r"(ADDR))

#define CP_ASYNC16(dst_u32, src) \
    asm volatile("cp.async.cg.shared.global [%0], [%1], 16;" \
                 :: "r"(dst_u32), "l"(src) : "memory")
#define CP_COMMIT() asm volatile("cp.async.commit_group;" ::: "memory")
#define CP_WAIT(n)  asm volatile("cp.async.wait_group %0;" :: "n"(n) : "memory")

// ---------------------------------------------------------------------------
// fp32 -> fp16 rounding pass (weights only)
// ---------------------------------------------------------------------------
__global__ __launch_bounds__(256) void round_kernel(const float4* __restrict__ in,
                                                    uint4* __restrict__ out, int n8) {
    int i = blockIdx.x * 256 + threadIdx.x;
    if (i < n8) {
        float4 v0 = in[i * 2], v1 = in[i * 2 + 1];
        uint4 r;
        r.x = pack_h2(v0.x, v0.y);
        r.y = pack_h2(v0.z, v0.w);
        r.z = pack_h2(v1.x, v1.y);
        r.w = pack_h2(v1.z, v1.w);
        out[i] = r;
    }
}

// ---------------------------------------------------------------------------
// fp16 mma.sync GEMM (unchanged, at mma.sync HMMA floor):
// CTA tile 64x256, 256 thr (8 warps: 2m x 4n, warp tile 32x64), 2 CTAs/SM.
// B: 3-stage cp.async. A: QKV=true fp32 LDG + fused fp16 cvt; else cp.async.
// QKV=true : fp16 scatter epilogue (roll+4 + window partition) into g_qkv.
// QKV=false: fp32 bias epilogue, dense row-major store.
// ---------------------------------------------------------------------------
template <bool QKV>
__global__ __launch_bounds__(256, 2)
void mma_gemm(const void* __restrict__ Av, const __half* __restrict__ Bw,
              const float* __restrict__ bias, void* __restrict__ Cv) {
    __half* sA = (__half*)dynsmem;          // [<=3][64][40] halves
    __half* sB = sA + 3 * 2560;             // [3][256][40] halves
    const uint32_t sA_u = smem_u32(sA);
    const uint32_t sB_u = smem_u32(sB);

    const float* A32 = (const float*)Av;
    const __half* A16 = (const __half*)Av;

    const int tid = threadIdx.x;
    const int wid = tid >> 5, lane = tid & 31;
    const int g = lane >> 2, tig = lane & 3;
    const int warp_m = wid & 1, warp_n = wid >> 1;   // 2 x 4 warp grid
    const int m0 = blockIdx.y * 64, n0 = blockIdx.x * 256;

    float acc[2][8][4];
#pragma unroll
    for (int i = 0; i < 2; ++i)
#pragma unroll
        for (int j = 0; j < 8; ++j)
#pragma unroll
            for (int c = 0; c < 4; ++c) acc[i][j][c] = 0.f;

    const int arow = tid >> 2, apart = tid & 3;

    float4 fa0, fa1;
    auto ldgA = [&](int s) {
        const float* src = A32 + (size_t)(m0 + arow) * DIM + s * 32 + apart * 8;
        fa0 = *(const float4*)src;
        fa1 = *(const float4*)(src + 4);
    };
    auto stsA = [&](int s) {
        uint4 u;
        u.x = pack_h2(fa0.x, fa0.y);
        u.y = pack_h2(fa0.z, fa0.w);
        u.z = pack_h2(fa1.x, fa1.y);
        u.w = pack_h2(fa1.z, fa1.w);
        *(uint4*)(sA + (s & 1) * 2560 + arow * 40 + apart * 8) = u;
    };

    auto issue = [&](int s) {
        const int k0 = s * 32;
        const int buf = s % 3;
        if (!QKV) {
            CP_ASYNC16(sA_u + (uint32_t)(buf * 2560 + arow * 40 + apart * 8) * 2u,
                       A16 + (size_t)(m0 + arow) * DIM + k0 + apart * 8);
        }
#pragma unroll
        for (int j = 0; j < 4; ++j) {
            int c = tid + j * 256;
            int row = c >> 2, part = c & 3;
            CP_ASYNC16(sB_u + (uint32_t)(buf * 10240 + row * 40 + part * 8) * 2u,
                       Bw + (size_t)(n0 + row) * DIM + k0 + part * 8);
        }
        CP_COMMIT();
    };

    if (QKV) {
        ldgA(0);
        stsA(0);
        ldgA(1);
    }
    issue(0);
    issue(1);

    const uint32_t a_lane_off = (uint32_t)((lane & 15) * 40 + (lane >> 4) * 8) * 2u;
    const uint32_t b_lane_off = (uint32_t)(lane * 40) * 2u;

#pragma unroll 1
    for (int s = 0; s < 8; ++s) {
        CP_WAIT(1);
        __syncthreads();
        if (QKV) {
            if (s < 7) stsA(s + 1);
            if (s < 6) ldgA(s + 2);
        }
        if (s < 6) issue(s + 2);

        const int abuf = QKV ? (s & 1) : (s % 3);
        const int bbuf = s % 3;
        const uint32_t aBase =
            sA_u + (uint32_t)(abuf * 2560 + warp_m * 32 * 40) * 2u + a_lane_off;
        const uint32_t bBase =
            sB_u + (uint32_t)(bbuf * 10240 + warp_n * 64 * 40) * 2u + b_lane_off;
#pragma unroll
        for (int kk = 0; kk < 2; ++kk) {
            uint32_t a[2][4];
#pragma unroll
            for (int mt = 0; mt < 2; ++mt)
                LDSM_X4(a[mt][0], a[mt][1], a[mt][2], a[mt][3],
                        aBase + (uint32_t)(mt * 16 * 40 + kk * 16) * 2u);
            uint32_t b0[8], b1[8];
#pragma unroll
            for (int half = 0; half < 2; ++half) {
                const uint32_t hb = bBase + (uint32_t)(half * 32 * 40) * 2u;
                LDSM_X4(b0[half * 4 + 0], b0[half * 4 + 1], b0[half * 4 + 2],
                        b0[half * 4 + 3], hb + (uint32_t)(kk * 16) * 2u);
                LDSM_X4(b1[half * 4 + 0], b1[half * 4 + 1], b1[half * 4 + 2],
                        b1[half * 4 + 3], hb + (uint32_t)(kk * 16 + 8) * 2u);
            }
#pragma unroll
            for (int nt = 0; nt < 8; ++nt)
#pragma unroll
                for (int mt = 0; mt < 2; ++mt)
                    mma_f16(acc[mt][nt], a[mt], b0[nt], b1[nt]);
        }
    }

    // epilogue
#pragma unroll
    for (int mt = 0; mt < 2; ++mt) {
#pragma unroll
        for (int e = 0; e < 2; ++e) {
            int row = m0 + warp_m * 32 + mt * 16 + e * 8 + g;
            if (QKV) {
                int b = row >> 16;
                int h = (row >> 8) & 255;
                int w = row & 255;
                int hs = (h + 4) & 255;        // cyclic shift +4
                int ws = (w + 4) & 255;
                int win = b * NWIN + ((hs >> 3) << 5) + (ws >> 3);
                int n = ((hs & 7) << 3) | (ws & 7);
                __half* dst = (__half*)Cv +
                              (((size_t)win * 3 + blockIdx.x) * N_TOK + n) * DIM;
#pragma unroll
                for (int nt = 0; nt < 8; ++nt) {
                    int cc = warp_n * 64 + nt * 8 + 2 * tig;
                    uint32_t p = pack_h2(acc[mt][nt][e * 2], acc[mt][nt][e * 2 + 1]);
                    *(uint32_t*)(dst + cc) = p;
                }
            } else {
                float* dst = (float*)Cv + (size_t)row * DIM;
#pragma unroll
                for (int nt = 0; nt < 8; ++nt) {
                    int col = warp_n * 64 + nt * 8 + 2 * tig;
                    float2 bi = *(const float2*)(bias + col);
                    float2 v = make_float2(acc[mt][nt][e * 2] + bi.x,
                                           acc[mt][nt][e * 2 + 1] + bi.y);
                    *(float2*)(dst + col) = v;
                }
            }
        }
    }
}

// ---------------------------------------------------------------------------
// fp16 tensor-core windowed attention, fully register-resident P:
// The m16n8 C-fragment layout of S IS the m16n8k16 A-fragment layout for PV
// (cols nt*8+2tig <-> k=kk*16+2tig with nt=2kk,2kk+1), so normalized P is
// packed pack_h2(accS*inv) straight into A-frag registers — no smem P at all.
// S-phase Q/K fragments via ldmatrix (GEMM-proven stride-40 addressing);
// PV B-frags via ldmatrix.trans on V[tok][d] (R12-proven).
// Per-head smem: Q[64][40] | K[64][40] | V[64][40], stride 7680 halves.
// Analytic Swin mask; register softmax. Store fuses unpartition + roll(-4,-4).
// ---------------------------------------------------------------------------
__global__ __launch_bounds__(128, 2) void attn_kernel() {
    __shared__ int sReg[64];
    __half* smemh = (__half*)dynsmem;

    const int win = blockIdx.x >> 1;
    const int hg = blockIdx.x & 1;
    const int wl = win & 1023;
    const int tid = threadIdx.x;
    const int wid = tid >> 5, lane = tid & 31;
    const int g = lane >> 2, tig = lane & 3;

    // cooperative load: Q,K,V all stored [tok][40] per head
#pragma unroll
    for (int m = 0; m < 3; ++m) {
        const uint4* src = (const uint4*)(g_qkv + ((size_t)win * 3 + m) * N_TOK * DIM);
#pragma unroll
        for (int it = 0; it < 8; ++it) {
            int idx = tid + it * 128;
            int tok = idx >> 4, ch8 = idx & 15;
            uint4 v = src[tok * 32 + hg * 16 + ch8];
            int head = ch8 >> 2, c0 = (ch8 & 3) * 8;
            *(uint4*)(smemh + head * 7680 + m * 2560 + tok * 40 + c0) = v;
        }
    }
    if (tid < 64) {
        int hs = ((wl >> 5) << 3) + (tid >> 3);
        int ws = ((wl & 31) << 3) + (tid & 7);
        int rh = (hs < 248) ? 0 : (hs < 252 ? 1 : 2);
        int rw = (ws < 248) ? 0 : (ws < 252 ? 1 : 2);
        sReg[tid] = rh * 3 + rw;
    }
    __syncthreads();

    const uint32_t headBase = smem_u32(smemh + wid * 7680);
    const uint32_t a_lane_off = (uint32_t)((lane & 15) * 40 + (lane >> 4) * 8) * 2u;
    const uint32_t qBase = headBase + a_lane_off;
    const uint32_t kBase = headBase + 2560u * 2u + (uint32_t)(lane * 40) * 2u;

    // ---- S = Q K^T (64x64), fragments via ldmatrix ----
    float accS[4][8][4];
#pragma unroll
    for (int i = 0; i < 4; ++i)
#pragma unroll
        for (int j = 0; j < 8; ++j)
#pragma unroll
            for (int c = 0; c < 4; ++c) accS[i][j][c] = 0.f;

#pragma unroll
    for (int kk = 0; kk < 2; ++kk) {
        uint32_t a[4][4];
#pragma unroll
        for (int mt = 0; mt < 4; ++mt)
            LDSM_X4(a[mt][0], a[mt][1], a[mt][2], a[mt][3],
                    qBase + (uint32_t)(mt * 16 * 40 + kk * 16) * 2u);
        uint32_t b0[8], b1[8];
#pragma unroll
        for (int half = 0; half < 2; ++half) {
            const uint32_t hb = kBase + (uint32_t)(half * 32 * 40) * 2u;
            LDSM_X4(b0[half * 4 + 0], b0[half * 4 + 1], b0[half * 4 + 2],
                    b0[half * 4 + 3], hb + (uint32_t)(kk * 16) * 2u);
            LDSM_X4(b1[half * 4 + 0], b1[half * 4 + 1], b1[half * 4 + 2],
                    b1[half * 4 + 3], hb + (uint32_t)(kk * 16 + 8) * 2u);
        }
#pragma unroll
        for (int nt = 0; nt < 8; ++nt)
#pragma unroll
            for (int mt = 0; mt < 4; ++mt)
                mma_f16(accS[mt][nt], a[mt], b0[nt], b1[nt]);
    }

    const bool edge = ((wl >> 5) == 31) || ((wl & 31) == 31);
#pragma unroll
    for (int mt = 0; mt < 4; ++mt)
#pragma unroll
        for (int nt = 0; nt < 8; ++nt)
#pragma unroll
            for (int c = 0; c < 4; ++c) accS[mt][nt][c] *= SCALE;
    if (edge) {
        int creg[2][8];
#pragma unroll
        for (int nt = 0; nt < 8; ++nt) {
            creg[0][nt] = sReg[nt * 8 + 2 * tig];
            creg[1][nt] = sReg[nt * 8 + 2 * tig + 1];
        }
#pragma unroll
        for (int mt = 0; mt < 4; ++mt)
#pragma unroll
            for (int e = 0; e < 2; ++e) {
                int rr = sReg[mt * 16 + e * 8 + g];
#pragma unroll
                for (int nt = 0; nt < 8; ++nt) {
                    if (creg[0][nt] != rr) accS[mt][nt][e * 2] -= 100.f;
                    if (creg[1][nt] != rr) accS[mt][nt][e * 2 + 1] -= 100.f;
                }
            }
    }

    // ---- softmax (register-resident) ----
    float inv[4][2];
#pragma unroll
    for (int mt = 0; mt < 4; ++mt) {
#pragma unroll
        for (int e = 0; e < 2; ++e) {
            float mx = -1e30f;
#pragma unroll
            for (int nt = 0; nt < 8; ++nt) {
                mx = fmaxf(mx, accS[mt][nt][e * 2]);
                mx = fmaxf(mx, accS[mt][nt][e * 2 + 1]);
            }
            mx = fmaxf(mx, __shfl_xor_sync(0xffffffffu, mx, 1));
            mx = fmaxf(mx, __shfl_xor_sync(0xffffffffu, mx, 2));
            float sum = 0.f;
#pragma unroll
            for (int nt = 0; nt < 8; ++nt) {
                float e0 = __expf(accS[mt][nt][e * 2] - mx);
                float e1 = __expf(accS[mt][nt][e * 2 + 1] - mx);
                accS[mt][nt][e * 2] = e0;
                accS[mt][nt][e * 2 + 1] = e1;
                sum += e0 + e1;
            }
            sum += __shfl_xor_sync(0xffffffffu, sum, 1);
            sum += __shfl_xor_sync(0xffffffffu, sum, 2);
            inv[mt][e] = 1.f / sum;
        }
    }

    // ---- pack normalized P into PV A-fragments (pure register op) ----
    // a-frag for (kk, mt): [0]=P[g][16kk+2tig..+1]      = accS[mt][2kk][0..1]*iv0
    //                      [1]=P[g+8][...]              = accS[mt][2kk][2..3]*iv1
    //                      [2]=P[g][16kk+8+2tig..+1]    = accS[mt][2kk+1][0..1]*iv0
    //                      [3]=P[g+8][...]              = accS[mt][2kk+1][2..3]*iv1
    uint32_t aP[4][4][4];
#pragma unroll
    for (int kk = 0; kk < 4; ++kk)
#pragma unroll
        for (int mt = 0; mt < 4; ++mt) {
            float iv0 = inv[mt][0], iv1 = inv[mt][1];
            aP[kk][mt][0] = pack_h2(accS[mt][2 * kk][0] * iv0,
                                    accS[mt][2 * kk][1] * iv0);
            aP[kk][mt][1] = pack_h2(accS[mt][2 * kk][2] * iv1,
                                    accS[mt][2 * kk][3] * iv1);
            aP[kk][mt][2] = pack_h2(accS[mt][2 * kk + 1][0] * iv0,
                                    accS[mt][2 * kk + 1][1] * iv0);
            aP[kk][mt][3] = pack_h2(accS[mt][2 * kk + 1][2] * iv1,
                                    accS[mt][2 * kk + 1][3] * iv1);
        }

    // ---- O = P V (64x32), B-frags via ldmatrix.x4.trans on V[tok][d] ----
    float accO[4][4][4];
#pragma unroll
    for (int i = 0; i < 4; ++i)
#pragma unroll
        for (int j = 0; j < 4; ++j)
#pragma unroll
            for (int c = 0; c < 4; ++c) accO[i][j][c] = 0.f;

    const int grp = lane >> 3, l8 = lane & 7;
    const uint32_t vLane = headBase + 5120u * 2u +
        (uint32_t)(((grp & 1) * 8 + l8) * 40 + (grp >> 1) * 8) * 2u;

#pragma unroll
    for (int kk = 0; kk < 4; ++kk) {
#pragma unroll
        for (int np = 0; np < 2; ++np) {
            uint32_t r0, r1, r2, r3;
            LDSM_X4_TRANS(r0, r1, r2, r3,
                          vLane + (uint32_t)(kk * 16 * 40 + np * 16) * 2u);
#pragma unroll
            for (int mt = 0; mt < 4; ++mt) {
                mma_f16(accO[mt][np * 2 + 0], aP[kk][mt], r0, r1);
                mma_f16(accO[mt][np * 2 + 1], aP[kk][mt], r2, r3);
            }
        }
    }

    // ---- store O fp16: unpartition + roll(-4,-4), pixel-major ----
    const int bimg = win >> 10;
#pragma unroll
    for (int mt = 0; mt < 4; ++mt) {
#pragma unroll
        for (int e = 0; e < 2; ++e) {
            int tok = mt * 16 + e * 8 + g;
            int hs = ((wl >> 5) << 3) + (tok >> 3);
            int ws = ((wl & 31) << 3) + (tok & 7);
            int h = (hs + 252) & 255;
            int w = (ws + 252) & 255;
            __half* dst = g_o + (((size_t)bimg * IMG + h) * IMG + w) * DIM +
                          (hg * 4 + wid) * HD;
#pragma unroll
            for (int nt = 0; nt < 4; ++nt) {
                uint32_t p = pack_h2(accO[mt][nt][e * 2], accO[mt][nt][e * 2 + 1]);
                *(uint32_t*)(dst + nt * 8 + 2 * tig) = p;
            }
        }
    }
}

// ---------------------------------------------------------------------------

extern "C" void kernel_launch(void* const* d_in, const int* in_sizes, int n_in,
                              void* d_out, int out_size) {
    const float* x      = (const float*)d_in[0];
    const float* qkv_w  = (const float*)d_in[1];
    const float* proj_w = (const float*)d_in[2];
    const float* proj_b = (const float*)d_in[3];
    float* out = (float*)d_out;

    __half* qkv_ptr = nullptr;
    __half* o_ptr = nullptr;
    __half* wq_ptr = nullptr;
    __half* wp_ptr = nullptr;
    cudaGetSymbolAddress((void**)&qkv_ptr, g_qkv);
    cudaGetSymbolAddress((void**)&o_ptr, g_o);
    cudaGetSymbolAddress((void**)&wq_ptr, g_wq);
    cudaGetSymbolAddress((void**)&wp_ptr, g_wp);

    const int gemm_smem = 3 * (2560 + 10240) * 2;   // 76800 B
    const int attn_smem = 4 * 7680 * 2;             // 61440 B
    cudaFuncSetAttribute(mma_gemm<true>, cudaFuncAttributeMaxDynamicSharedMemorySize,
                         gemm_smem);
    cudaFuncSetAttribute(mma_gemm<false>, cudaFuncAttributeMaxDynamicSharedMemorySize,
                         gemm_smem);
    cudaFuncSetAttribute(attn_kernel, cudaFuncAttributeMaxDynamicSharedMemorySize,
                         attn_smem);

    // 0) fp16-round the weights (x conversion is fused into the qkv GEMM)
    round_kernel<<<196608 / 8 / 256, 256>>>((const float4*)qkv_w, (uint4*)wq_ptr,
                                            196608 / 8);
    round_kernel<<<65536 / 8 / 256, 256>>>((const float4*)proj_w, (uint4*)wp_ptr,
                                           65536 / 8);

    // 1) qkv projection (fp16 mma, fused fp32->fp16 A conversion)
    //    + shift + window partition. grid (3, 4096): blockIdx.x = q/k/v.
    mma_gemm<true><<<dim3(3, NPIX / 64), 256, gemm_smem>>>(x, wq_ptr, nullptr,
                                                           qkv_ptr);
    // 2) fp16 tensor-core shifted-window attention (register-resident P)
    attn_kernel<<<BATCH * NWIN * 2, 128, attn_smem>>>();
    // 3) output projection (fp16 mma) + bias, fp32 out
    mma_gemm<false><<<dim3(1, NPIX / 64), 256, gemm_smem>>>(o_ptr, wp_ptr, proj_b,
                                                            out);
}

// round 14
// speedup vs baseline: 1.0183x; 1.0183x over previous
#include <cuda_runtime.h>
#include <cuda_fp16.h>
#include <cstdint>

#define DIM 256
#define HEADS 8
#define HD 32
#define N_TOK 64
#define IMG 256
#define BATCH 4
#define NWIN 1024
#define NPIX 262144
#define SCALE 0.17677669529663687f

// scratch (static device globals: allocation-free per harness rules)
__device__ __align__(256) __half g_qkv[201326592];  // [4096 win][3][64 tok][256 ch]
__device__ __align__(256) __half g_o[67108864];     // attn output (fp16, pre-rounded)
__device__ __align__(256) __half g_wq[196608];      // fp16 qkv_w
__device__ __align__(256) __half g_wp[65536];       // fp16 proj_w

extern __shared__ float dynsmem[];

__device__ __forceinline__ uint32_t pack_h2(float a, float b) {
    __half2 h = __floats2half2_rn(a, b);
    uint32_t r;
    memcpy(&r, &h, 4);
    return r;
}

__device__ __forceinline__ void mma_f16(float c[4], const uint32_t a[4],
                                        uint32_t b0, uint32_t b1) {
    asm volatile(
        "mma.sync.aligned.m16n8k16.row.col.f32.f16.f16.f32 "
        "{%0,%1,%2,%3}, {%4,%5,%6,%7}, {%8,%9}, {%0,%1,%2,%3};"
        : "+f"(c[0]), "+f"(c[1]), "+f"(c[2]), "+f"(c[3])
        : "r"(a[0]), "r"(a[1]), "r"(a[2]), "r"(a[3]), "r"(b0), "r"(b1));
}

__device__ __forceinline__ uint32_t smem_u32(const void* p) {
    uint32_t a;
    asm("{ .reg .u64 t; cvta.to.shared.u64 t, %1; cvt.u32.u64 %0, t; }"
        : "=r"(a) : "l"(p));
    return a;
}

#define LDSM_X4(R0, R1, R2, R3, ADDR) \
    asm volatile("ldmatrix.sync.aligned.m8n8.x4.shared.b16 {%0,%1,%2,%3}, [%4];" \
                 : "=r"(R0), "=r"(R1), "=r"(R2), "=r"(R3) : "r"(ADDR))

#define LDSM_X4_TRANS(R0, R1, R2, R3, ADDR) \
    asm volatile("ldmatrix.sync.aligned.m8n8.x4.trans.shared.b16 {%0,%1,%2,%3}, [%4];" \
                 : "=r"(R0), "=r"(R1), "=r"(R2), "=r"(R3) : "r"(ADDR))

#define CP_ASYNC16(dst_u32, src) \
    asm volatile("cp.async.cg.shared.global [%0], [%1], 16;" \
                 :: "r"(dst_u32), "l"(src) : "memory")
#define CP_COMMIT() asm volatile("cp.async.commit_group;" ::: "memory")
#define CP_WAIT(n)  asm volatile("cp.async.wait_group %0;" :: "n"(n) : "memory")

// ---------------------------------------------------------------------------
// fp32 -> fp16 rounding pass (weights only)
// ---------------------------------------------------------------------------
__global__ __launch_bounds__(256) void round_kernel(const float4* __restrict__ in,
                                                    uint4* __restrict__ out, int n8) {
    int i = blockIdx.x * 256 + threadIdx.x;
    if (i < n8) {
        float4 v0 = in[i * 2], v1 = in[i * 2 + 1];
        uint4 r;
        r.x = pack_h2(v0.x, v0.y);
        r.y = pack_h2(v0.z, v0.w);
        r.z = pack_h2(v1.x, v1.y);
        r.w = pack_h2(v1.z, v1.w);
        out[i] = r;
    }
}

// ---------------------------------------------------------------------------
// fp16 mma.sync GEMM (unchanged, at mma.sync HMMA floor):
// CTA tile 64x256, 256 thr (8 warps: 2m x 4n, warp tile 32x64), 2 CTAs/SM.
// B: 3-stage cp.async. A: QKV=true fp32 LDG + fused fp16 cvt; else cp.async.
// QKV=true : fp16 scatter epilogue (roll+4 + window partition) into g_qkv.
// QKV=false: fp32 bias epilogue, dense row-major store.
// ---------------------------------------------------------------------------
template <bool QKV>
__global__ __launch_bounds__(256, 2)
void mma_gemm(const void* __restrict__ Av, const __half* __restrict__ Bw,
              const float* __restrict__ bias, void* __restrict__ Cv) {
    __half* sA = (__half*)dynsmem;          // [<=3][64][40] halves
    __half* sB = sA + 3 * 2560;             // [3][256][40] halves
    const uint32_t sA_u = smem_u32(sA);
    const uint32_t sB_u = smem_u32(sB);

    const float* A32 = (const float*)Av;
    const __half* A16 = (const __half*)Av;

    const int tid = threadIdx.x;
    const int wid = tid >> 5, lane = tid & 31;
    const int g = lane >> 2, tig = lane & 3;
    const int warp_m = wid & 1, warp_n = wid >> 1;   // 2 x 4 warp grid
    const int m0 = blockIdx.y * 64, n0 = blockIdx.x * 256;

    float acc[2][8][4];
#pragma unroll
    for (int i = 0; i < 2; ++i)
#pragma unroll
        for (int j = 0; j < 8; ++j)
#pragma unroll
            for (int c = 0; c < 4; ++c) acc[i][j][c] = 0.f;

    const int arow = tid >> 2, apart = tid & 3;

    float4 fa0, fa1;
    auto ldgA = [&](int s) {
        const float* src = A32 + (size_t)(m0 + arow) * DIM + s * 32 + apart * 8;
        fa0 = *(const float4*)src;
        fa1 = *(const float4*)(src + 4);
    };
    auto stsA = [&](int s) {
        uint4 u;
        u.x = pack_h2(fa0.x, fa0.y);
        u.y = pack_h2(fa0.z, fa0.w);
        u.z = pack_h2(fa1.x, fa1.y);
        u.w = pack_h2(fa1.z, fa1.w);
        *(uint4*)(sA + (s & 1) * 2560 + arow * 40 + apart * 8) = u;
    };

    auto issue = [&](int s) {
        const int k0 = s * 32;
        const int buf = s % 3;
        if (!QKV) {
            CP_ASYNC16(sA_u + (uint32_t)(buf * 2560 + arow * 40 + apart * 8) * 2u,
                       A16 + (size_t)(m0 + arow) * DIM + k0 + apart * 8);
        }
#pragma unroll
        for (int j = 0; j < 4; ++j) {
            int c = tid + j * 256;
            int row = c >> 2, part = c & 3;
            CP_ASYNC16(sB_u + (uint32_t)(buf * 10240 + row * 40 + part * 8) * 2u,
                       Bw + (size_t)(n0 + row) * DIM + k0 + part * 8);
        }
        CP_COMMIT();
    };

    if (QKV) {
        ldgA(0);
        stsA(0);
        ldgA(1);
    }
    issue(0);
    issue(1);

    const uint32_t a_lane_off = (uint32_t)((lane & 15) * 40 + (lane >> 4) * 8) * 2u;
    const uint32_t b_lane_off = (uint32_t)(lane * 40) * 2u;

#pragma unroll 1
    for (int s = 0; s < 8; ++s) {
        CP_WAIT(1);
        __syncthreads();
        if (QKV) {
            if (s < 7) stsA(s + 1);
            if (s < 6) ldgA(s + 2);
        }
        if (s < 6) issue(s + 2);

        const int abuf = QKV ? (s & 1) : (s % 3);
        const int bbuf = s % 3;
        const uint32_t aBase =
            sA_u + (uint32_t)(abuf * 2560 + warp_m * 32 * 40) * 2u + a_lane_off;
        const uint32_t bBase =
            sB_u + (uint32_t)(bbuf * 10240 + warp_n * 64 * 40) * 2u + b_lane_off;
#pragma unroll
        for (int kk = 0; kk < 2; ++kk) {
            uint32_t a[2][4];
#pragma unroll
            for (int mt = 0; mt < 2; ++mt)
                LDSM_X4(a[mt][0], a[mt][1], a[mt][2], a[mt][3],
                        aBase + (uint32_t)(mt * 16 * 40 + kk * 16) * 2u);
            uint32_t b0[8], b1[8];
#pragma unroll
            for (int half = 0; half < 2; ++half) {
                const uint32_t hb = bBase + (uint32_t)(half * 32 * 40) * 2u;
                LDSM_X4(b0[half * 4 + 0], b0[half * 4 + 1], b0[half * 4 + 2],
                        b0[half * 4 + 3], hb + (uint32_t)(kk * 16) * 2u);
                LDSM_X4(b1[half * 4 + 0], b1[half * 4 + 1], b1[half * 4 + 2],
                        b1[half * 4 + 3], hb + (uint32_t)(kk * 16 + 8) * 2u);
            }
#pragma unroll
            for (int nt = 0; nt < 8; ++nt)
#pragma unroll
                for (int mt = 0; mt < 2; ++mt)
                    mma_f16(acc[mt][nt], a[mt], b0[nt], b1[nt]);
        }
    }

    // epilogue
#pragma unroll
    for (int mt = 0; mt < 2; ++mt) {
#pragma unroll
        for (int e = 0; e < 2; ++e) {
            int row = m0 + warp_m * 32 + mt * 16 + e * 8 + g;
            if (QKV) {
                int b = row >> 16;
                int h = (row >> 8) & 255;
                int w = row & 255;
                int hs = (h + 4) & 255;        // cyclic shift +4
                int ws = (w + 4) & 255;
                int win = b * NWIN + ((hs >> 3) << 5) + (ws >> 3);
                int n = ((hs & 7) << 3) | (ws & 7);
                __half* dst = (__half*)Cv +
                              (((size_t)win * 3 + blockIdx.x) * N_TOK + n) * DIM;
#pragma unroll
                for (int nt = 0; nt < 8; ++nt) {
                    int cc = warp_n * 64 + nt * 8 + 2 * tig;
                    uint32_t p = pack_h2(acc[mt][nt][e * 2], acc[mt][nt][e * 2 + 1]);
                    *(uint32_t*)(dst + cc) = p;
                }
            } else {
                float* dst = (float*)Cv + (size_t)row * DIM;
#pragma unroll
                for (int nt = 0; nt < 8; ++nt) {
                    int col = warp_n * 64 + nt * 8 + 2 * tig;
                    float2 bi = *(const float2*)(bias + col);
                    float2 v = make_float2(acc[mt][nt][e * 2] + bi.x,
                                           acc[mt][nt][e * 2 + 1] + bi.y);
                    *(float2*)(dst + col) = v;
                }
            }
        }
    }
}

// ---------------------------------------------------------------------------
// fp16 tensor-core windowed attention (R12 structure + full ldmatrix frags):
// - smem P round-trip KEPT (register-P raised regs to 205 and regressed R13);
// - S-phase Q/K fragments via LDSM_X4 (stride-40, GEMM-proven);
// - PV A-fragments from P[64][72] via LDSM_X4 (stride 72 halves -> phase rows
//   hit banks 4r..4r+3, all 32 banks once: conflict-free);
// - V B-frags via LDSM_X4_TRANS on V[tok][d] (R12-proven).
// Per-head smem: Q[64][40] | K[64][40] | V[64][40], stride 7680 halves;
// P[64][72] overlays Q+K. Analytic Swin mask; register softmax.
// Store fuses unpartition + roll(-4,-4) into pixel-major fp16 g_o.
// ---------------------------------------------------------------------------
__global__ __launch_bounds__(128, 3) void attn_kernel() {
    __shared__ int sReg[64];
    __half* smemh = (__half*)dynsmem;

    const int win = blockIdx.x >> 1;
    const int hg = blockIdx.x & 1;
    const int wl = win & 1023;
    const int tid = threadIdx.x;
    const int wid = tid >> 5, lane = tid & 31;
    const int g = lane >> 2, tig = lane & 3;

    // cooperative load: Q,K,V all stored [tok][40] per head
#pragma unroll
    for (int m = 0; m < 3; ++m) {
        const uint4* src = (const uint4*)(g_qkv + ((size_t)win * 3 + m) * N_TOK * DIM);
#pragma unroll
        for (int it = 0; it < 8; ++it) {
            int idx = tid + it * 128;
            int tok = idx >> 4, ch8 = idx & 15;
            uint4 v = src[tok * 32 + hg * 16 + ch8];
            int head = ch8 >> 2, c0 = (ch8 & 3) * 8;
            *(uint4*)(smemh + head * 7680 + m * 2560 + tok * 40 + c0) = v;
        }
    }
    if (tid < 64) {
        int hs = ((wl >> 5) << 3) + (tid >> 3);
        int ws = ((wl & 31) << 3) + (tid & 7);
        int rh = (hs < 248) ? 0 : (hs < 252 ? 1 : 2);
        int rw = (ws < 248) ? 0 : (ws < 252 ? 1 : 2);
        sReg[tid] = rh * 3 + rw;
    }
    __syncthreads();

    const uint32_t headBase = smem_u32(smemh + wid * 7680);
    const uint32_t a_lane40 = (uint32_t)((lane & 15) * 40 + (lane >> 4) * 8) * 2u;
    const uint32_t qBase = headBase + a_lane40;
    const uint32_t kBase = headBase + 2560u * 2u + (uint32_t)(lane * 40) * 2u;
    __half* hP = smemh + wid * 7680;          // P overlays Q,K after S phase

    // ---- S = Q K^T (64x64), fragments via ldmatrix ----
    float accS[4][8][4];
#pragma unroll
    for (int i = 0; i < 4; ++i)
#pragma unroll
        for (int j = 0; j < 8; ++j)
#pragma unroll
            for (int c = 0; c < 4; ++c) accS[i][j][c] = 0.f;

#pragma unroll
    for (int kk = 0; kk < 2; ++kk) {
        uint32_t a[4][4];
#pragma unroll
        for (int mt = 0; mt < 4; ++mt)
            LDSM_X4(a[mt][0], a[mt][1], a[mt][2], a[mt][3],
                    qBase + (uint32_t)(mt * 16 * 40 + kk * 16) * 2u);
        uint32_t b0[8], b1[8];
#pragma unroll
        for (int half = 0; half < 2; ++half) {
            const uint32_t hb = kBase + (uint32_t)(half * 32 * 40) * 2u;
            LDSM_X4(b0[half * 4 + 0], b0[half * 4 + 1], b0[half * 4 + 2],
                    b0[half * 4 + 3], hb + (uint32_t)(kk * 16) * 2u);
            LDSM_X4(b1[half * 4 + 0], b1[half * 4 + 1], b1[half * 4 + 2],
                    b1[half * 4 + 3], hb + (uint32_t)(kk * 16 + 8) * 2u);
        }
#pragma unroll
        for (int nt = 0; nt < 8; ++nt)
#pragma unroll
            for (int mt = 0; mt < 4; ++mt)
                mma_f16(accS[mt][nt], a[mt], b0[nt], b1[nt]);
    }

    const bool edge = ((wl >> 5) == 31) || ((wl & 31) == 31);
#pragma unroll
    for (int mt = 0; mt < 4; ++mt)
#pragma unroll
        for (int nt = 0; nt < 8; ++nt)
#pragma unroll
            for (int c = 0; c < 4; ++c) accS[mt][nt][c] *= SCALE;
    if (edge) {
        int creg[2][8];
#pragma unroll
        for (int nt = 0; nt < 8; ++nt) {
            creg[0][nt] = sReg[nt * 8 + 2 * tig];
            creg[1][nt] = sReg[nt * 8 + 2 * tig + 1];
        }
#pragma unroll
        for (int mt = 0; mt < 4; ++mt)
#pragma unroll
            for (int e = 0; e < 2; ++e) {
                int rr = sReg[mt * 16 + e * 8 + g];
#pragma unroll
                for (int nt = 0; nt < 8; ++nt) {
                    if (creg[0][nt] != rr) accS[mt][nt][e * 2] -= 100.f;
                    if (creg[1][nt] != rr) accS[mt][nt][e * 2 + 1] -= 100.f;
                }
            }
    }

    // ---- softmax (register-resident) ----
    float inv[4][2];
#pragma unroll
    for (int mt = 0; mt < 4; ++mt) {
#pragma unroll
        for (int e = 0; e < 2; ++e) {
            float mx = -1e30f;
#pragma unroll
            for (int nt = 0; nt < 8; ++nt) {
                mx = fmaxf(mx, accS[mt][nt][e * 2]);
                mx = fmaxf(mx, accS[mt][nt][e * 2 + 1]);
            }
            mx = fmaxf(mx, __shfl_xor_sync(0xffffffffu, mx, 1));
            mx = fmaxf(mx, __shfl_xor_sync(0xffffffffu, mx, 2));
            float sum = 0.f;
#pragma unroll
            for (int nt = 0; nt < 8; ++nt) {
                float e0 = __expf(accS[mt][nt][e * 2] - mx);
                float e1 = __expf(accS[mt][nt][e * 2 + 1] - mx);
                accS[mt][nt][e * 2] = e0;
                accS[mt][nt][e * 2 + 1] = e1;
                sum += e0 + e1;
            }
            sum += __shfl_xor_sync(0xffffffffu, sum, 1);
            sum += __shfl_xor_sync(0xffffffffu, sum, 2);
            inv[mt][e] = 1.f / sum;
        }
    }

    __syncwarp();   // all Q/K reads done before P overlays them
    // ---- write P (normalized fp16) to smem [64][72] ----
#pragma unroll
    for (int mt = 0; mt < 4; ++mt)
#pragma unroll
        for (int e = 0; e < 2; ++e) {
            float iv = inv[mt][e];
            __half* prow = hP + (mt * 16 + e * 8 + g) * 72;
#pragma unroll
            for (int nt = 0; nt < 8; ++nt) {
                uint32_t p = pack_h2(accS[mt][nt][e * 2] * iv,
                                     accS[mt][nt][e * 2 + 1] * iv);
                *(uint32_t*)(prow + nt * 8 + 2 * tig) = p;
            }
        }
    __syncwarp();

    // ---- O = P V (64x32): A-frags via LDSM on P, B-frags via LDSM.trans on V
    float accO[4][4][4];
#pragma unroll
    for (int i = 0; i < 4; ++i)
#pragma unroll
        for (int j = 0; j < 4; ++j)
#pragma unroll
            for (int c = 0; c < 4; ++c) accO[i][j][c] = 0.f;

    const uint32_t pBase =
        headBase + (uint32_t)((lane & 15) * 72 + (lane >> 4) * 8) * 2u;
    const int grp = lane >> 3, l8 = lane & 7;
    const uint32_t vLane = headBase + 5120u * 2u +
        (uint32_t)(((grp & 1) * 8 + l8) * 40 + (grp >> 1) * 8) * 2u;

#pragma unroll
    for (int kk = 0; kk < 4; ++kk) {
        uint32_t a[4][4];
#pragma unroll
        for (int mt = 0; mt < 4; ++mt)
            LDSM_X4(a[mt][0], a[mt][1], a[mt][2], a[mt][3],
                    pBase + (uint32_t)(mt * 16 * 72 + kk * 16) * 2u);
#pragma unroll
        for (int np = 0; np < 2; ++np) {
            uint32_t r0, r1, r2, r3;
            LDSM_X4_TRANS(r0, r1, r2, r3,
                          vLane + (uint32_t)(kk * 16 * 40 + np * 16) * 2u);
#pragma unroll
            for (int mt = 0; mt < 4; ++mt) {
                mma_f16(accO[mt][np * 2 + 0], a[mt], r0, r1);
                mma_f16(accO[mt][np * 2 + 1], a[mt], r2, r3);
            }
        }
    }

    // ---- store O fp16: unpartition + roll(-4,-4), pixel-major ----
    const int bimg = win >> 10;
#pragma unroll
    for (int mt = 0; mt < 4; ++mt) {
#pragma unroll
        for (int e = 0; e < 2; ++e) {
            int tok = mt * 16 + e * 8 + g;
            int hs = ((wl >> 5) << 3) + (tok >> 3);
            int ws = ((wl & 31) << 3) + (tok & 7);
            int h = (hs + 252) & 255;
            int w = (ws + 252) & 255;
            __half* dst = g_o + (((size_t)bimg * IMG + h) * IMG + w) * DIM +
                          (hg * 4 + wid) * HD;
#pragma unroll
            for (int nt = 0; nt < 4; ++nt) {
                uint32_t p = pack_h2(accO[mt][nt][e * 2], accO[mt][nt][e * 2 + 1]);
                *(uint32_t*)(dst + nt * 8 + 2 * tig) = p;
            }
        }
    }
}

// ---------------------------------------------------------------------------

extern "C" void kernel_launch(void* const* d_in, const int* in_sizes, int n_in,
                              void* d_out, int out_size) {
    const float* x      = (const float*)d_in[0];
    const float* qkv_w  = (const float*)d_in[1];
    const float* proj_w = (const float*)d_in[2];
    const float* proj_b = (const float*)d_in[3];
    float* out = (float*)d_out;

    __half* qkv_ptr = nullptr;
    __half* o_ptr = nullptr;
    __half* wq_ptr = nullptr;
    __half* wp_ptr = nullptr;
    cudaGetSymbolAddress((void**)&qkv_ptr, g_qkv);
    cudaGetSymbolAddress((void**)&o_ptr, g_o);
    cudaGetSymbolAddress((void**)&wq_ptr, g_wq);
    cudaGetSymbolAddress((void**)&wp_ptr, g_wp);

    const int gemm_smem = 3 * (2560 + 10240) * 2;   // 76800 B
    const int attn_smem = 4 * 7680 * 2;             // 61440 B
    cudaFuncSetAttribute(mma_gemm<true>, cudaFuncAttributeMaxDynamicSharedMemorySize,
                         gemm_smem);
    cudaFuncSetAttribute(mma_gemm<false>, cudaFuncAttributeMaxDynamicSharedMemorySize,
                         gemm_smem);
    cudaFuncSetAttribute(attn_kernel, cudaFuncAttributeMaxDynamicSharedMemorySize,
                         attn_smem);

    // 0) fp16-round the weights (x conversion is fused into the qkv GEMM)
    round_kernel<<<196608 / 8 / 256, 256>>>((const float4*)qkv_w, (uint4*)wq_ptr,
                                            196608 / 8);
    round_kernel<<<65536 / 8 / 256, 256>>>((const float4*)proj_w, (uint4*)wp_ptr,
                                           65536 / 8);

    // 1) qkv projection (fp16 mma, fused fp32->fp16 A conversion)
    //    + shift + window partition. grid (3, 4096): blockIdx.x = q/k/v.
    mma_gemm<true><<<dim3(3, NPIX / 64), 256, gemm_smem>>>(x, wq_ptr, nullptr,
                                                           qkv_ptr);
    // 2) fp16 tensor-core shifted-window attention (full ldmatrix fragments)
    attn_kernel<<<BATCH * NWIN * 2, 128, attn_smem>>>();
    // 3) output projection (fp16 mma) + bias, fp32 out
    mma_gemm<false><<<dim3(1, NPIX / 64), 256, gemm_smem>>>(o_ptr, wp_ptr, proj_b,
                                                            out);
}